// round 14
// baseline (speedup 1.0000x reference)
#include <cuda_runtime.h>

#define BB 512
#define NN 90
#define DD 1024
#define KK 45
#define THREADS 256
#define WARPS 8
#define LAG 50                               // gather lags score by LAG batches
#define QTOT (BB + LAG)
#define TOTAL_TASKS (12 * QTOT)

// Device-global scratch (no allocation allowed)
__device__ unsigned g_task_counter;
__device__ unsigned g_done;
__device__ unsigned g_arrive[BB];
__device__ unsigned g_ready[BB];
__device__ float    g_scores[BB][NN];
__device__ int      g_sel_idx[BB][KK];
__device__ float    g_sel_w[BB][KK];

__global__ __launch_bounds__(THREADS, 4)
void multig_pool_kernel(const float* __restrict__ x_sc,
                        const float* __restrict__ x_fc,
                        const float* __restrict__ pool_w,
                        const float* __restrict__ multi_w,
                        const float* __restrict__ multi_b,
                        float* __restrict__ out)
{
    __shared__ __align__(16) float spw[DD];
    __shared__ float s_scores[NN];
    __shared__ int   sel_idx[KK];
    __shared__ float sel_w[KK];
    __shared__ float red[WARPS];
    __shared__ float s_invnorm;
    __shared__ unsigned s_task;
    __shared__ unsigned s_last_scorer;

    const int tid  = threadIdx.x;
    const int wid  = tid >> 5;
    const int lane = tid & 31;

    // ---- Once per CTA: stage pool_w, compute 1/||pool_w|| ----
    float pw2 = 0.f;
    #pragma unroll
    for (int i = 0; i < 4; i++) {
        float v = pool_w[tid + i * THREADS];
        spw[tid + i * THREADS] = v;
        pw2 += v * v;
    }
    #pragma unroll
    for (int off = 16; off; off >>= 1) pw2 += __shfl_xor_sync(0xffffffffu, pw2, off);
    if (lane == 0) red[wid] = pw2;
    __syncthreads();
    if (tid == 0) {
        float s = 0.f;
        #pragma unroll
        for (int i = 0; i < WARPS; i++) s += red[i];
        s_invnorm = rsqrtf(s);
    }
    __syncthreads();

    const float inv_norm = s_invnorm;
    const float mw0 = multi_w[0];
    const float mw1 = multi_w[1];
    const float4* __restrict__ pw4 = (const float4*)spw;

    // ---- Persistent interleaved task stream, 12 tasks per batch ----
    // t = 12q + r.  r<8: score eighth r of batch q; the LAST-finishing score
    // task also computes the top-45 once and publishes it.  r>=8: gather
    // quarter (r-8) of batch q-LAG using the published selection.
    // Dequeue distance 12*LAG = 600 >= concurrency 592 (no spins in practice).
    for (;;) {
        if (tid == 0) s_task = atomicAdd(&g_task_counter, 1u);
        __syncthreads();
        const unsigned t = s_task;
        if (t >= TOTAL_TASKS) break;

        const unsigned q = t / 12u;
        const unsigned r = t % 12u;

        if (r < 8u) {
            // ============ SCORE EIGHTH: batch q, nodes r + 8j ============
            if (q < BB) {
                const int b = (int)q;
                const int e = (int)r;
                const float* __restrict__ xb_sc = x_sc + (size_t)b * NN * DD;
                const float* __restrict__ xb_fc = x_fc + (size_t)b * NN * DD;

                const int cnt = (NN - e + 7) >> 3;    // 12 or 11
                for (int j = wid; j < cnt; j += WARPS) {
                    const int n = e + 8 * j;
                    const float4* rs = (const float4*)(xb_sc + (size_t)n * DD);
                    const float4* rf = (const float4*)(xb_fc + (size_t)n * DD);
                    float dsc = 0.f, dfc = 0.f;
                    #pragma unroll
                    for (int i = 0; i < 8; i++) {
                        int jj = lane + i * 32;
                        float4 a = rs[jj];
                        float4 c = rf[jj];
                        float4 p = pw4[jj];
                        dsc += a.x * p.x + a.y * p.y + a.z * p.z + a.w * p.w;
                        dfc += c.x * p.x + c.y * p.y + c.z * p.z + c.w * p.w;
                    }
                    #pragma unroll
                    for (int off = 16; off; off >>= 1) {
                        dsc += __shfl_xor_sync(0xffffffffu, dsc, off);
                        dfc += __shfl_xor_sync(0xffffffffu, dfc, off);
                    }
                    if (lane == 0) {
                        float t0 = tanhf(dsc * inv_norm);
                        float t1 = tanhf(dfc * inv_norm);
                        float z  = t0 * mw0 + t1 * mw1 + multi_b[n];
                        g_scores[b][n] = 1.f / (1.f + expf(-z));
                    }
                }
                __syncthreads();                 // all my g_scores writes done
                if (tid == 0) {
                    __threadfence();
                    s_last_scorer = (atomicAdd(&g_arrive[b], 1u) == 7u) ? 1u : 0u;
                }
                __syncthreads();

                // Last scorer computes + publishes the selection ONCE.
                if (s_last_scorer) {
                    if (tid < NN) s_scores[tid] = __ldcg(&g_scores[b][tid]);
                    __syncthreads();
                    if (tid < NN) {
                        float my = s_scores[tid];
                        int rk = 0;
                        #pragma unroll 10
                        for (int j = 0; j < NN; j++) {
                            float sj = s_scores[j];
                            rk += (sj > my) || (sj == my && j < tid);
                        }
                        if (rk < KK) {
                            g_sel_idx[b][rk] = tid;
                            g_sel_w[b][rk]   = my;
                        }
                    }
                    __syncthreads();
                    if (tid == 0) {
                        __threadfence();
                        atomicExch(&g_ready[b], 1u);
                    }
                }
            }
        } else {
            // ======= GATHER QUARTER: batch q-LAG, rows (r-8)+4m =======
            if (q >= LAG && q - LAG < BB) {
                const int b  = (int)(q - LAG);
                const int qt = (int)(r - 8u);

                if (tid == 0) {
                    while (atomicAdd(&g_ready[b], 0u) == 0u) { }
                }
                __syncthreads();

                // Load published selection (45 idx + 45 weights)
                if (tid < KK) {
                    sel_idx[tid] = __ldcg(&g_sel_idx[b][tid]);
                    sel_w[tid]   = __ldcg(&g_sel_w[b][tid]);
                }
                __syncthreads();

                const float* __restrict__ xb_sc = x_sc + (size_t)b * NN * DD;
                const float* __restrict__ xb_fc = x_fc + (size_t)b * NN * DD;
                float* __restrict__ out_sc = out + (size_t)b * KK * DD;
                float* __restrict__ out_fc = out + (size_t)BB * KK * DD
                                                 + (size_t)b * KK * DD;

                // Output rows qt, qt+4, ... over both tensors (2*KK = 90)
                const int cnt2 = (2 * KK - qt + 3) >> 2;   // 23 or 22
                for (int m = wid; m < cnt2; m += WARPS) {
                    const int rr = qt + 4 * m;
                    const bool is_sc = (rr < KK);
                    const int  k = is_sc ? rr : rr - KK;
                    const int  n = sel_idx[k];
                    const float w = sel_w[k];
                    const float4* src = (const float4*)
                        ((is_sc ? xb_sc : xb_fc) + (size_t)n * DD);
                    float4* dst = (float4*)
                        ((is_sc ? out_sc : out_fc) + (size_t)k * DD);
                    #pragma unroll
                    for (int i = 0; i < 8; i++) {
                        int j = lane + i * 32;
                        float4 v = src[j];
                        v.x *= w; v.y *= w; v.z *= w; v.w *= w;
                        dst[j] = v;
                    }
                }
            }
        }
        // no trailing sync — loop-top sync covers reuse hazards
    }

    // ---- Last CTA out resets device state for the next graph replay ----
    __shared__ unsigned s_is_last;
    if (tid == 0) {
        unsigned d = atomicAdd(&g_done, 1u) + 1u;
        s_is_last = (d == gridDim.x) ? 1u : 0u;
    }
    __syncthreads();
    if (s_is_last) {
        for (int i = tid; i < BB; i += THREADS) {
            g_arrive[i] = 0;
            g_ready[i]  = 0;
        }
        __syncthreads();
        if (tid == 0) {
            g_task_counter = 0;
            __threadfence();
            g_done = 0;
        }
    }
}

extern "C" void kernel_launch(void* const* d_in, const int* in_sizes, int n_in,
                              void* d_out, int out_size)
{
    const float* x_sc    = (const float*)d_in[0];
    const float* x_fc    = (const float*)d_in[1];
    const float* pool_w  = (const float*)d_in[2];
    const float* multi_w = (const float*)d_in[3];
    const float* multi_b = (const float*)d_in[4];
    float* out = (float*)d_out;

    static int grid = 0;
    if (grid == 0) {
        int sm = 0;
        cudaDeviceGetAttribute(&sm, cudaDevAttrMultiProcessorCount, 0);
        if (sm <= 0) sm = 148;
        grid = 4 * sm;   // 4 CTAs/SM x 256 thr
    }

    multig_pool_kernel<<<grid, THREADS>>>(x_sc, x_fc, pool_w, multi_w, multi_b, out);
}